// round 1
// baseline (speedup 1.0000x reference)
#include <cuda_runtime.h>

#define N_NODES 50000
#define N_EDGES 300000
#define F_IN    256
#define HID     256
#define N_CLS   128

// ---------------- scratch (no allocation allowed) ----------------
__device__ float g_gemm[N_NODES * HID];   // GEMM output of current layer
__device__ float g_ping[N_NODES * HID];   // aggregated features (layer out / next in)
__device__ float g_pong[N_NODES * HID];
__device__ float g_dis [N_NODES];         // deg -> rsqrt(deg)
__device__ float g_pool[N_CLS];

// ---------------- utility ----------------
__global__ void zero_kernel(float* __restrict__ p, int n) {
    int i = blockIdx.x * blockDim.x + threadIdx.x;
    if (i < n) p[i] = 0.f;
}

__global__ void deg_kernel(const int* __restrict__ dst, float* __restrict__ deg) {
    int i = blockIdx.x * blockDim.x + threadIdx.x;
    if (i < N_EDGES) atomicAdd(&deg[dst[i]], 1.0f);
}

// deg -> dis = rsqrt(deg + 1)   (+1 = self loop; deg >= 1 always)
__global__ void dis_kernel(float* __restrict__ d) {
    int i = blockIdx.x * blockDim.x + threadIdx.x;
    if (i < N_NODES) d[i] = rsqrtf(d[i] + 1.0f);
}

// ---------------- GEMM: out[M,N] = X[M,K] @ W[K,N] ----------------
// 64x64 tile, TK=16, 256 threads, 4x4 micro-tile per thread, fp32.
#define TM 64
#define TN 64
#define TK 16
__global__ void gemm_kernel(const float* __restrict__ X, const float* __restrict__ W,
                            float* __restrict__ out, int M, int K, int N) {
    __shared__ float As[TK][TM + 1];
    __shared__ float Bs[TK][TN + 1];
    const int bm = blockIdx.x * TM;
    const int bn = blockIdx.y * TN;
    const int tid = threadIdx.x;
    const int tm = (tid / 16) * 4;
    const int tn = (tid % 16) * 4;

    float acc[4][4] = {};

    for (int k0 = 0; k0 < K; k0 += TK) {
        // load A tile (64 rows x 16 k), coalesced along k
        #pragma unroll
        for (int i = tid; i < TM * TK; i += 256) {
            int m = i >> 4, k = i & 15;
            int gm = bm + m;
            As[k][m] = (gm < M) ? X[gm * K + k0 + k] : 0.f;
        }
        // load B tile (16 k x 64 n), coalesced along n
        #pragma unroll
        for (int i = tid; i < TK * TN; i += 256) {
            int k = i >> 6, n = i & 63;
            Bs[k][n] = W[(k0 + k) * N + bn + n];
        }
        __syncthreads();
        #pragma unroll
        for (int k = 0; k < TK; k++) {
            float a[4], b[4];
            #pragma unroll
            for (int i = 0; i < 4; i++) a[i] = As[k][tm + i];
            #pragma unroll
            for (int j = 0; j < 4; j++) b[j] = Bs[k][tn + j];
            #pragma unroll
            for (int i = 0; i < 4; i++)
                #pragma unroll
                for (int j = 0; j < 4; j++)
                    acc[i][j] = fmaf(a[i], b[j], acc[i][j]);
        }
        __syncthreads();
    }
    #pragma unroll
    for (int i = 0; i < 4; i++) {
        int gm = bm + tm + i;
        if (gm < M) {
            #pragma unroll
            for (int j = 0; j < 4; j++)
                out[gm * N + bn + tn + j] = acc[i][j];
        }
    }
}

// ---------------- edge scatter: out[dst] += H[src] * dis[src]*dis[dst] ----------------
// one warp per edge; vectorized gather, scalar atomic scatter.
__global__ void scatter_kernel(const float* __restrict__ H,
                               const int* __restrict__ src, const int* __restrict__ dst,
                               const float* __restrict__ dis,
                               float* __restrict__ out, int F) {
    int warp = (blockIdx.x * blockDim.x + threadIdx.x) >> 5;
    int lane = threadIdx.x & 31;
    if (warp >= N_EDGES) return;
    int s = src[warp], d = dst[warp];
    float nrm = dis[s] * dis[d];
    const float4* hs = (const float4*)(H + (long)s * F);
    float* od = out + (long)d * F;
    int nv = F >> 2;
    for (int j = lane; j < nv; j += 32) {
        float4 v = hs[j];
        atomicAdd(od + 4 * j + 0, v.x * nrm);
        atomicAdd(od + 4 * j + 1, v.y * nrm);
        atomicAdd(od + 4 * j + 2, v.z * nrm);
        atomicAdd(od + 4 * j + 3, v.w * nrm);
    }
}

// ---------------- epilogue: out += H*dis^2 (self loop) + bias, optional relu ----------------
__global__ void epilogue_kernel(float* __restrict__ out, const float* __restrict__ H,
                                const float* __restrict__ dis, const float* __restrict__ bias,
                                int F, int do_relu) {
    int idx = blockIdx.x * blockDim.x + threadIdx.x;
    if (idx >= N_NODES * F) return;
    int m = idx / F, f = idx - m * F;
    float d = dis[m];
    float v = out[idx] + H[idx] * d * d + bias[f];
    if (do_relu) v = fmaxf(v, 0.f);
    out[idx] = v;
}

// ---------------- pooling: pooled[f] = sum_m H[m,f] ----------------
__global__ void pool_kernel(const float* __restrict__ H, float* __restrict__ pooled) {
    int f = threadIdx.x;  // N_CLS threads
    float s = 0.f;
    for (int m = blockIdx.x; m < N_NODES; m += gridDim.x)
        s += H[(long)m * N_CLS + f];
    atomicAdd(&pooled[f], s);
}

// ---------------- final: out[0:128]=pooled, out[128:256]=log_softmax ----------------
__global__ void final_kernel(const float* __restrict__ pooled, float* __restrict__ out) {
    __shared__ float red[N_CLS];
    int f = threadIdx.x;
    float v = pooled[f];
    red[f] = v;
    __syncthreads();
    for (int s = N_CLS / 2; s > 0; s >>= 1) {
        if (f < s) red[f] = fmaxf(red[f], red[f + s]);
        __syncthreads();
    }
    float mx = red[0];
    __syncthreads();
    red[f] = expf(v - mx);
    __syncthreads();
    for (int s = N_CLS / 2; s > 0; s >>= 1) {
        if (f < s) red[f] += red[f + s];
        __syncthreads();
    }
    float lse = mx + logf(red[0]);
    out[f] = v;
    out[N_CLS + f] = v - lse;
}

// ---------------- host ----------------
static void run_layer(const float* in, const float* W, const float* b,
                      float* gemm_buf, float* out_buf, const float* dis,
                      const int* src, const int* dst, int K, int Fout, int do_relu) {
    dim3 ggrid((N_NODES + TM - 1) / TM, Fout / TN);
    gemm_kernel<<<ggrid, 256>>>(in, W, gemm_buf, N_NODES, K, Fout);
    int n = N_NODES * Fout;
    zero_kernel<<<(n + 255) / 256, 256>>>(out_buf, n);
    scatter_kernel<<<(N_EDGES * 32 + 255) / 256, 256>>>(gemm_buf, src, dst, dis, out_buf, Fout);
    epilogue_kernel<<<(n + 255) / 256, 256>>>(out_buf, gemm_buf, dis, b, Fout, do_relu);
}

extern "C" void kernel_launch(void* const* d_in, const int* in_sizes, int n_in,
                              void* d_out, int out_size) {
    const float* x   = (const float*)d_in[0];
    const int*   ei  = (const int*)  d_in[1];
    const float* W1  = (const float*)d_in[2];
    const float* b1  = (const float*)d_in[3];
    const float* W2  = (const float*)d_in[4];
    const float* b2  = (const float*)d_in[5];
    const float* W3  = (const float*)d_in[6];
    const float* b3  = (const float*)d_in[7];
    const float* W4  = (const float*)d_in[8];
    const float* b4  = (const float*)d_in[9];
    float* out = (float*)d_out;

    const int* src = ei;
    const int* dst = ei + N_EDGES;

    float *gemm_buf, *ping, *pong, *dis, *pooled;
    cudaGetSymbolAddress((void**)&gemm_buf, g_gemm);
    cudaGetSymbolAddress((void**)&ping,     g_ping);
    cudaGetSymbolAddress((void**)&pong,     g_pong);
    cudaGetSymbolAddress((void**)&dis,      g_dis);
    cudaGetSymbolAddress((void**)&pooled,   g_pool);

    // degree -> dis
    zero_kernel<<<(N_NODES + 255) / 256, 256>>>(dis, N_NODES);
    deg_kernel<<<(N_EDGES + 255) / 256, 256>>>(dst, dis);
    dis_kernel<<<(N_NODES + 255) / 256, 256>>>(dis);

    // 4 GCN layers
    run_layer(x,    W1, b1, gemm_buf, ping, dis, src, dst, F_IN, HID,   1);
    run_layer(ping, W2, b2, gemm_buf, pong, dis, src, dst, HID,  HID,   1);
    run_layer(pong, W3, b3, gemm_buf, ping, dis, src, dst, HID,  HID,   1);
    run_layer(ping, W4, b4, gemm_buf, pong, dis, src, dst, HID,  N_CLS, 0);

    // global add pool + log_softmax
    zero_kernel<<<1, N_CLS>>>(pooled, N_CLS);
    pool_kernel<<<512, N_CLS>>>(pong, pooled);
    final_kernel<<<1, N_CLS>>>(pooled, out);
}

// round 3
// speedup vs baseline: 2.3043x; 2.3043x over previous
#include <cuda_runtime.h>

#define N_NODES 50000
#define N_EDGES 300000
#define F_IN    256
#define HID     256
#define N_CLS   128

// ---------------- scratch ----------------
__device__ float g_gemm[N_NODES * HID];
__device__ float g_ping[N_NODES * HID];
__device__ float g_pong[N_NODES * HID];
__device__ float g_dis [N_NODES];
__device__ float g_pool[N_CLS];
__device__ int   g_deg [N_NODES];
__device__ int   g_off [N_NODES + 1];
__device__ int   g_cur [N_NODES];
__device__ int   g_csrc[N_EDGES];

// ---------------- small utils ----------------
__global__ void zero_f(float* __restrict__ p, int n) {
    int i = blockIdx.x * blockDim.x + threadIdx.x;
    if (i < n) p[i] = 0.f;
}
__global__ void zero_i(int* __restrict__ p, int n) {
    int i = blockIdx.x * blockDim.x + threadIdx.x;
    if (i < n) p[i] = 0;
}
__global__ void deg_count(const int* __restrict__ dst, int* __restrict__ deg) {
    int i = blockIdx.x * blockDim.x + threadIdx.x;
    if (i < N_EDGES) atomicAdd(&deg[dst[i]], 1);
}
__global__ void dis_kernel(const int* __restrict__ deg, float* __restrict__ dis) {
    int i = blockIdx.x * blockDim.x + threadIdx.x;
    if (i < N_NODES) dis[i] = rsqrtf((float)deg[i] + 1.0f);
}

// single-block scan over N_NODES (exclusive), writes off + cur copy
__global__ void scan_kernel(const int* __restrict__ deg, int* __restrict__ off,
                            int* __restrict__ cur) {
    __shared__ int s[1024];
    __shared__ int carry_s;
    int tid = threadIdx.x;
    if (tid == 0) carry_s = 0;
    __syncthreads();
    for (int base = 0; base < N_NODES; base += 1024) {
        int i = base + tid;
        int v = (i < N_NODES) ? deg[i] : 0;
        s[tid] = v;
        __syncthreads();
        #pragma unroll
        for (int d = 1; d < 1024; d <<= 1) {
            int t = (tid >= d) ? s[tid - d] : 0;
            __syncthreads();
            s[tid] += t;
            __syncthreads();
        }
        int carry = carry_s;
        if (i < N_NODES) {
            int excl = carry + s[tid] - v;
            off[i] = excl;
            cur[i] = excl;
        }
        __syncthreads();
        if (tid == 1023) carry_s = carry + s[1023];
        __syncthreads();
    }
    if (tid == 0) off[N_NODES] = carry_s;
}

__global__ void place_edges(const int* __restrict__ src, const int* __restrict__ dst,
                            int* __restrict__ cur, int* __restrict__ csrc) {
    int e = blockIdx.x * blockDim.x + threadIdx.x;
    if (e < N_EDGES) {
        int pos = atomicAdd(&cur[dst[e]], 1);
        csrc[pos] = src[e];
    }
}

// ---------------- SGEMM: C[M,N] = A[M,K] @ B[K,N], 128x128x16, 8x8 micro ----------------
#define BM 128
#define BN 128
#define BK 16
__global__ void __launch_bounds__(256, 2)
sgemm(const float* __restrict__ A, const float* __restrict__ B,
      float* __restrict__ C, int M, int K, int N) {
    __shared__ float As[BK][BM + 4];
    __shared__ float Bs[BK][BN];
    const int bm = blockIdx.x * BM;
    const int bn = blockIdx.y * BN;
    const int tid = threadIdx.x;
    const int tx = tid & 15, ty = tid >> 4;
    const int tm = ty * 8, tn = tx * 8;

    const int ar = tid >> 2;        // 0..63 (two rows: ar, ar+64)
    const int ak = (tid & 3) * 4;   // k offset 0,4,8,12
    const int br = tid >> 5;        // 0..7 (two k-rows: br, br+8)
    const int bc = (tid & 31) * 4;  // n offset

    float acc[8][8] = {};

    for (int k0 = 0; k0 < K; k0 += BK) {
        #pragma unroll
        for (int i = 0; i < 2; i++) {
            int gm = bm + ar + i * 64;
            float4 v = (gm < M) ? *(const float4*)(A + (size_t)gm * K + k0 + ak)
                                : make_float4(0.f, 0.f, 0.f, 0.f);
            As[ak + 0][ar + i * 64] = v.x;
            As[ak + 1][ar + i * 64] = v.y;
            As[ak + 2][ar + i * 64] = v.z;
            As[ak + 3][ar + i * 64] = v.w;
        }
        #pragma unroll
        for (int i = 0; i < 2; i++) {
            int kk = br + i * 8;
            *(float4*)&Bs[kk][bc] = *(const float4*)(B + (size_t)(k0 + kk) * N + bn + bc);
        }
        __syncthreads();
        #pragma unroll
        for (int k = 0; k < BK; k++) {
            float a[8], b[8];
            *(float4*)(a)     = *(float4*)&As[k][tm];
            *(float4*)(a + 4) = *(float4*)&As[k][tm + 4];
            *(float4*)(b)     = *(float4*)&Bs[k][tn];
            *(float4*)(b + 4) = *(float4*)&Bs[k][tn + 4];
            #pragma unroll
            for (int i = 0; i < 8; i++)
                #pragma unroll
                for (int j = 0; j < 8; j++)
                    acc[i][j] = fmaf(a[i], b[j], acc[i][j]);
        }
        __syncthreads();
    }
    #pragma unroll
    for (int i = 0; i < 8; i++) {
        int gm = bm + tm + i;
        if (gm < M) {
            float* cp = C + (size_t)gm * N + bn + tn;
            *(float4*)(cp)     = *(float4*)&acc[i][0];
            *(float4*)(cp + 4) = *(float4*)&acc[i][4];
        }
    }
}

// ---------------- CSR aggregation, F=256, fused self-loop + bias + relu ----------------
// one warp per node, each lane owns 8 features (2 float4)
__global__ void agg256(const float* __restrict__ H, const int* __restrict__ off,
                       const int* __restrict__ csrc, const float* __restrict__ dis,
                       const float* __restrict__ bias, float* __restrict__ out) {
    int node = blockIdx.x * (blockDim.x >> 5) + (threadIdx.x >> 5);
    if (node >= N_NODES) return;
    int lane = threadIdx.x & 31;
    float dd = dis[node];
    float4 a0 = {0,0,0,0}, a1 = {0,0,0,0};
    int beg = off[node], end = off[node + 1];
    for (int e = beg; e < end; e++) {
        int s = csrc[e];                 // warp-uniform broadcast load
        float nrm = dis[s] * dd;
        const float4* hp = (const float4*)(H + (size_t)s * 256);
        float4 v0 = hp[lane * 2], v1 = hp[lane * 2 + 1];
        a0.x = fmaf(v0.x, nrm, a0.x); a0.y = fmaf(v0.y, nrm, a0.y);
        a0.z = fmaf(v0.z, nrm, a0.z); a0.w = fmaf(v0.w, nrm, a0.w);
        a1.x = fmaf(v1.x, nrm, a1.x); a1.y = fmaf(v1.y, nrm, a1.y);
        a1.z = fmaf(v1.z, nrm, a1.z); a1.w = fmaf(v1.w, nrm, a1.w);
    }
    // self loop
    float sl = dd * dd;
    const float4* gp = (const float4*)(H + (size_t)node * 256);
    float4 s0 = gp[lane * 2], s1 = gp[lane * 2 + 1];
    a0.x = fmaf(s0.x, sl, a0.x); a0.y = fmaf(s0.y, sl, a0.y);
    a0.z = fmaf(s0.z, sl, a0.z); a0.w = fmaf(s0.w, sl, a0.w);
    a1.x = fmaf(s1.x, sl, a1.x); a1.y = fmaf(s1.y, sl, a1.y);
    a1.z = fmaf(s1.z, sl, a1.z); a1.w = fmaf(s1.w, sl, a1.w);
    // bias + relu
    const float4* bp = (const float4*)bias;
    float4 b0 = bp[lane * 2], b1 = bp[lane * 2 + 1];
    a0.x = fmaxf(a0.x + b0.x, 0.f); a0.y = fmaxf(a0.y + b0.y, 0.f);
    a0.z = fmaxf(a0.z + b0.z, 0.f); a0.w = fmaxf(a0.w + b0.w, 0.f);
    a1.x = fmaxf(a1.x + b1.x, 0.f); a1.y = fmaxf(a1.y + b1.y, 0.f);
    a1.z = fmaxf(a1.z + b1.z, 0.f); a1.w = fmaxf(a1.w + b1.w, 0.f);
    float4* op = (float4*)(out + (size_t)node * 256);
    op[lane * 2]     = a0;
    op[lane * 2 + 1] = a1;
}

// ---------------- last layer: F=128 aggregation fused into global add pool ----------------
// warp per node, lane owns 4 features; block-level smem reduce then one atomic per feature
__global__ void agg_pool128(const float* __restrict__ H, const int* __restrict__ off,
                            const int* __restrict__ csrc, const float* __restrict__ dis,
                            const float* __restrict__ bias, float* __restrict__ pooled) {
    __shared__ float sm[N_CLS];
    int tid = threadIdx.x;
    if (tid < N_CLS) sm[tid] = 0.f;
    __syncthreads();
    int node = blockIdx.x * (blockDim.x >> 5) + (tid >> 5);
    int lane = tid & 31;
    if (node < N_NODES) {
        float dd = dis[node];
        float4 a = {0,0,0,0};
        int beg = off[node], end = off[node + 1];
        for (int e = beg; e < end; e++) {
            int s = csrc[e];
            float nrm = dis[s] * dd;
            float4 v = ((const float4*)(H + (size_t)s * 128))[lane];
            a.x = fmaf(v.x, nrm, a.x); a.y = fmaf(v.y, nrm, a.y);
            a.z = fmaf(v.z, nrm, a.z); a.w = fmaf(v.w, nrm, a.w);
        }
        float sl = dd * dd;
        float4 s4 = ((const float4*)(H + (size_t)node * 128))[lane];
        a.x = fmaf(s4.x, sl, a.x); a.y = fmaf(s4.y, sl, a.y);
        a.z = fmaf(s4.z, sl, a.z); a.w = fmaf(s4.w, sl, a.w);
        float4 b = ((const float4*)bias)[lane];
        a.x += b.x; a.y += b.y; a.z += b.z; a.w += b.w;
        atomicAdd(&sm[lane * 4 + 0], a.x);
        atomicAdd(&sm[lane * 4 + 1], a.y);
        atomicAdd(&sm[lane * 4 + 2], a.z);
        atomicAdd(&sm[lane * 4 + 3], a.w);
    }
    __syncthreads();
    if (tid < N_CLS) atomicAdd(&pooled[tid], sm[tid]);
}

// ---------------- final: out[0:128]=pooled, out[128:256]=log_softmax ----------------
__global__ void final_kernel(const float* __restrict__ pooled, float* __restrict__ out) {
    __shared__ float red[N_CLS];
    int f = threadIdx.x;
    float v = pooled[f];
    red[f] = v;
    __syncthreads();
    for (int s = N_CLS / 2; s > 0; s >>= 1) {
        if (f < s) red[f] = fmaxf(red[f], red[f + s]);
        __syncthreads();
    }
    float mx = red[0];
    __syncthreads();
    red[f] = expf(v - mx);
    __syncthreads();
    for (int s = N_CLS / 2; s > 0; s >>= 1) {
        if (f < s) red[f] += red[f + s];
        __syncthreads();
    }
    float lse = mx + logf(red[0]);
    out[f] = v;
    out[N_CLS + f] = v - lse;
}

// ---------------- host ----------------
extern "C" void kernel_launch(void* const* d_in, const int* in_sizes, int n_in,
                              void* d_out, int out_size) {
    const float* x  = (const float*)d_in[0];
    const int*   ei = (const int*)  d_in[1];
    const float* W1 = (const float*)d_in[2];
    const float* b1 = (const float*)d_in[3];
    const float* W2 = (const float*)d_in[4];
    const float* b2 = (const float*)d_in[5];
    const float* W3 = (const float*)d_in[6];
    const float* b3 = (const float*)d_in[7];
    const float* W4 = (const float*)d_in[8];
    const float* b4 = (const float*)d_in[9];
    float* out = (float*)d_out;

    const int* src = ei;
    const int* dst = ei + N_EDGES;

    float *gemm_buf, *ping, *pong, *dis, *pooled;
    int *deg, *off, *cur, *csrc;
    cudaGetSymbolAddress((void**)&gemm_buf, g_gemm);
    cudaGetSymbolAddress((void**)&ping,     g_ping);
    cudaGetSymbolAddress((void**)&pong,     g_pong);
    cudaGetSymbolAddress((void**)&dis,      g_dis);
    cudaGetSymbolAddress((void**)&pooled,   g_pool);
    cudaGetSymbolAddress((void**)&deg,      g_deg);
    cudaGetSymbolAddress((void**)&off,      g_off);
    cudaGetSymbolAddress((void**)&cur,      g_cur);
    cudaGetSymbolAddress((void**)&csrc,     g_csrc);

    // CSR build + norms
    zero_i<<<(N_NODES + 255) / 256, 256>>>(deg, N_NODES);
    deg_count<<<(N_EDGES + 255) / 256, 256>>>(dst, deg);
    dis_kernel<<<(N_NODES + 255) / 256, 256>>>(deg, dis);
    scan_kernel<<<1, 1024>>>(deg, off, cur);
    place_edges<<<(N_EDGES + 255) / 256, 256>>>(src, dst, cur, csrc);

    const int AGG_BLOCKS = (N_NODES * 32 + 255) / 256;
    dim3 g256((N_NODES + BM - 1) / BM, HID / BN);
    dim3 g128((N_NODES + BM - 1) / BM, N_CLS / BN);

    // layer 1
    sgemm<<<g256, 256>>>(x, W1, gemm_buf, N_NODES, F_IN, HID);
    agg256<<<AGG_BLOCKS, 256>>>(gemm_buf, off, csrc, dis, b1, ping);
    // layer 2
    sgemm<<<g256, 256>>>(ping, W2, gemm_buf, N_NODES, HID, HID);
    agg256<<<AGG_BLOCKS, 256>>>(gemm_buf, off, csrc, dis, b2, pong);
    // layer 3
    sgemm<<<g256, 256>>>(pong, W3, gemm_buf, N_NODES, HID, HID);
    agg256<<<AGG_BLOCKS, 256>>>(gemm_buf, off, csrc, dis, b3, ping);
    // layer 4 + pool
    sgemm<<<g128, 256>>>(ping, W4, gemm_buf, N_NODES, HID, N_CLS);
    zero_f<<<1, N_CLS>>>(pooled, N_CLS);
    agg_pool128<<<AGG_BLOCKS, 256>>>(gemm_buf, off, csrc, dis, b4, pooled);

    final_kernel<<<1, N_CLS>>>(pooled, out);
}

// round 10
// speedup vs baseline: 2.9944x; 1.2995x over previous
#include <cuda_runtime.h>
#include <cuda_bf16.h>
#include <cstdint>

#define N_NODES 50000
#define N_EDGES 300000
#define F_IN    256
#define HID     256
#define N_CLS   128

// ======================= helpers =======================
__device__ __forceinline__ uint32_t smem_u32(const void* p) {
    uint32_t a;
    asm("{ .reg .u64 t; cvta.to.shared.u64 t, %1; cvt.u32.u64 %0, t; }" : "=r"(a) : "l"(p));
    return a;
}
__device__ __forceinline__ void cp16(uint32_t dst, const void* src) {
    asm volatile("cp.async.cg.shared.global [%0], [%1], 16;" :: "r"(dst), "l"(src) : "memory");
}
__device__ __forceinline__ void cp_commit_wait() {
    asm volatile("cp.async.commit_group;" ::: "memory");
    asm volatile("cp.async.wait_group 0;" ::: "memory");
}
__device__ __forceinline__ void ldmx4(uint32_t& r0, uint32_t& r1, uint32_t& r2, uint32_t& r3,
                                      uint32_t addr) {
    asm volatile("ldmatrix.sync.aligned.m8n8.x4.shared.b16 {%0,%1,%2,%3}, [%4];"
                 : "=r"(r0), "=r"(r1), "=r"(r2), "=r"(r3) : "r"(addr));
}
__device__ __forceinline__ void mma_bf16(float* d, const uint32_t* a, const uint32_t* b) {
    asm volatile("mma.sync.aligned.m16n8k16.row.col.f32.bf16.bf16.f32 "
                 "{%0,%1,%2,%3}, {%4,%5,%6,%7}, {%8,%9}, {%0,%1,%2,%3};"
                 : "+f"(d[0]), "+f"(d[1]), "+f"(d[2]), "+f"(d[3])
                 : "r"(a[0]), "r"(a[1]), "r"(a[2]), "r"(a[3]), "r"(b[0]), "r"(b[1]));
}
__device__ __forceinline__ void split1(float v, __nv_bfloat16& h, __nv_bfloat16& l) {
    h = __float2bfloat16(v);
    l = __float2bfloat16(v - __bfloat162float(h));
}

// ======================= scratch =======================
__device__ float         g_gemm[N_NODES * HID];          // fp32 GEMM output
__device__ __nv_bfloat16 g_ah[N_NODES * HID];
__device__ __nv_bfloat16 g_al[N_NODES * HID];
__device__ __nv_bfloat16 g_bh[N_NODES * HID];
__device__ __nv_bfloat16 g_bl[N_NODES * HID];
__device__ __nv_bfloat16 g_wth[HID * HID];
__device__ __nv_bfloat16 g_wtl[HID * HID];
__device__ float g_dis [N_NODES];
__device__ float g_pool[N_CLS];
__device__ int   g_deg [N_NODES];
__device__ int   g_off [N_NODES + 1];
__device__ int   g_cur [N_NODES];
__device__ int   g_csrc[N_EDGES];
__device__ int   g_part[256];

#define NBLK 196   // ceil(50000/256)

// ======================= small utils =======================
__global__ void zero_f(float* __restrict__ p, int n) {
    int i = blockIdx.x * blockDim.x + threadIdx.x;
    if (i < n) p[i] = 0.f;
}
__global__ void zero_i(int* __restrict__ p, int n) {
    int i = blockIdx.x * blockDim.x + threadIdx.x;
    if (i < n) p[i] = 0;
}
__global__ void deg_count(const int* __restrict__ dst, int* __restrict__ deg) {
    int i = blockIdx.x * blockDim.x + threadIdx.x;
    if (i < N_EDGES) atomicAdd(&deg[dst[i]], 1);
}
__global__ void dis_kernel(const int* __restrict__ deg, float* __restrict__ dis) {
    int i = blockIdx.x * blockDim.x + threadIdx.x;
    if (i < N_NODES) dis[i] = rsqrtf((float)deg[i] + 1.0f);
}

// --------- 3-phase scan ---------
__global__ void part_reduce(const int* __restrict__ deg, int* __restrict__ part) {
    int i = blockIdx.x * 256 + threadIdx.x;
    int v = (i < N_NODES) ? deg[i] : 0;
    #pragma unroll
    for (int o = 16; o; o >>= 1) v += __shfl_down_sync(0xFFFFFFFFu, v, o);
    __shared__ int ws[8];
    if ((threadIdx.x & 31) == 0) ws[threadIdx.x >> 5] = v;
    __syncthreads();
    if (threadIdx.x == 0) {
        int s = 0;
        #pragma unroll
        for (int j = 0; j < 8; j++) s += ws[j];
        part[blockIdx.x] = s;
    }
}
__global__ void scan_parts(int* __restrict__ part, int* __restrict__ total_out) {
    __shared__ int s[256];
    int t = threadIdx.x;
    int v = (t < NBLK) ? part[t] : 0;
    s[t] = v;
    __syncthreads();
    for (int d = 1; d < 256; d <<= 1) {
        int x = (t >= d) ? s[t - d] : 0;
        __syncthreads();
        s[t] += x;
        __syncthreads();
    }
    if (t < NBLK) part[t] = s[t] - v;
    if (t == 255) total_out[0] = s[255];
}
__global__ void block_scan(const int* __restrict__ deg, const int* __restrict__ part,
                           int* __restrict__ off, int* __restrict__ cur) {
    int i = blockIdx.x * 256 + threadIdx.x;
    int v = (i < N_NODES) ? deg[i] : 0;
    int lane = threadIdx.x & 31, w = threadIdx.x >> 5;
    int inc = v;
    #pragma unroll
    for (int o = 1; o < 32; o <<= 1) {
        int x = __shfl_up_sync(0xFFFFFFFFu, inc, o);
        if (lane >= o) inc += x;
    }
    __shared__ int ws[8], wo[8];
    if (lane == 31) ws[w] = inc;
    __syncthreads();
    if (threadIdx.x == 0) {
        int a = 0;
        #pragma unroll
        for (int j = 0; j < 8; j++) { wo[j] = a; a += ws[j]; }
    }
    __syncthreads();
    int excl = part[blockIdx.x] + wo[w] + inc - v;
    if (i < N_NODES) { off[i] = excl; cur[i] = excl; }
}
__global__ void place_edges(const int* __restrict__ src, const int* __restrict__ dst,
                            int* __restrict__ cur, int* __restrict__ csrc) {
    int e = blockIdx.x * blockDim.x + threadIdx.x;
    if (e < N_EDGES) {
        int pos = atomicAdd(&cur[dst[e]], 1);
        csrc[pos] = src[e];
    }
}

// --------- splits ---------
__global__ void split_x(const float* __restrict__ x, __nv_bfloat16* __restrict__ xh,
                        __nv_bfloat16* __restrict__ xl, int n) {
    int i = blockIdx.x * blockDim.x + threadIdx.x;
    if (i < n) {
        float v = x[i];
        __nv_bfloat16 h, l;
        split1(v, h, l);
        xh[i] = h;
        xl[i] = l;
    }
}
// W [K, N] row-major -> Wt hi/lo [N, K] bf16
__global__ void split_w(const float* __restrict__ W, int K, int N,
                        __nv_bfloat16* __restrict__ Wth, __nv_bfloat16* __restrict__ Wtl) {
    int i = blockIdx.x * blockDim.x + threadIdx.x;
    if (i < K * N) {
        int k = i / N, n = i - k * N;
        __nv_bfloat16 h, l;
        split1(W[i], h, l);
        Wth[(size_t)n * K + k] = h;
        Wtl[(size_t)n * K + k] = l;
    }
}

// ======================= bf16 split GEMM via mma.sync =======================
// C[M, Nf] = (Ah+Al)[M,256] @ (Wt hi+lo)[Nf,256]^T, CTA tile 128x128, K chunks of 64.
#define OFF_AH 0
#define OFF_AL 16384
#define OFF_BH 32768
#define OFF_BL 49152
#define GSMEM  65536

__global__ void __launch_bounds__(256, 2)
bf16_gemm(const __nv_bfloat16* __restrict__ Ah, const __nv_bfloat16* __restrict__ Al,
          const __nv_bfloat16* __restrict__ Bh, const __nv_bfloat16* __restrict__ Bl,
          float* __restrict__ C, int M, int Nf) {
    extern __shared__ char smem[];
    const uint32_t sbase = smem_u32(smem);
    const int tid = threadIdx.x;
    const int bm = blockIdx.x * 128, bn = blockIdx.y * 128;
    const int warp = tid >> 5, lane = tid & 31;
    const int wm = (warp & 1) * 64, wn = (warp >> 1) * 32;

    float acc[4][4][4];
    #pragma unroll
    for (int i = 0; i < 4; i++)
        #pragma unroll
        for (int j = 0; j < 4; j++)
            #pragma unroll
            for (int q = 0; q < 4; q++) acc[i][j][q] = 0.f;

    const int lrow = tid >> 3;          // 0..31
    const int lcb  = (tid & 7) * 16;    // byte col within 128B row
    const int lcol = (tid & 7) * 8;     // element col

    for (int kc = 0; kc < 256; kc += 64) {
        #pragma unroll
        for (int p = 0; p < 4; p++) {
            int r = p * 32 + lrow;      // 0..127: A row within tile / B n-row
            uint32_t sw = (uint32_t)(r * 128 + (lcb ^ ((r & 7) << 4)));
            int gm = bm + r;
            if (gm > M - 1) gm = M - 1;
            cp16(sbase + OFF_AH + sw, Ah + (size_t)gm * 256 + kc + lcol);
            cp16(sbase + OFF_AL + sw, Al + (size_t)gm * 256 + kc + lcol);
            cp16(sbase + OFF_BH + sw, Bh + (size_t)(bn + r) * 256 + kc + lcol);
            cp16(sbase + OFF_BL + sw, Bl + (size_t)(bn + r) * 256 + kc + lcol);
        }
        cp_commit_wait();
        __syncthreads();

        #pragma unroll
        for (int ks = 0; ks < 4; ks++) {
            const int kb = ks * 32 + ((lane >> 4) << 4);
            // B fragments: 4 n8-octets, hi and lo
            uint32_t bh[4][2], bl[4][2];
            #pragma unroll
            for (int g = 0; g < 2; g++) {
                int nr = wn + g * 16 + (lane & 15);
                uint32_t ad = sbase + OFF_BH + nr * 128 + (kb ^ ((nr & 7) << 4));
                uint32_t r0, r1, r2, r3;
                ldmx4(r0, r1, r2, r3, ad);
                bh[g * 2][0] = r0; bh[g * 2][1] = r2;
                bh[g * 2 + 1][0] = r1; bh[g * 2 + 1][1] = r3;
                ldmx4(r0, r1, r2, r3, ad + (OFF_BL - OFF_BH));
                bl[g * 2][0] = r0; bl[g * 2][1] = r2;
                bl[g * 2 + 1][0] = r1; bl[g * 2 + 1][1] = r3;
            }
            #pragma unroll
            for (int mi = 0; mi < 4; mi++) {
                int mr = wm + mi * 16 + (lane & 15);
                uint32_t ad = sbase + OFF_AH + mr * 128 + (kb ^ ((mr & 7) << 4));
                uint32_t ah[4], al[4];
                ldmx4(ah[0], ah[1], ah[2], ah[3], ad);
                ldmx4(al[0], al[1], al[2], al[3], ad + (OFF_AL - OFF_AH));
                #pragma unroll
                for (int ni = 0; ni < 4; ni++) {
                    mma_bf16(acc[mi][ni], ah, bh[ni]);   // hi*hi
                    mma_bf16(acc[mi][ni], ah, bl[ni]);   // hi*lo
                    mma_bf16(acc[mi][ni], al, bh[ni]);   // lo*hi
                }
            }
        }
        __syncthreads();
    }

    // epilogue: fragment -> C
    #pragma unroll
    for (int mi = 0; mi < 4; mi++) {
        int r0 = bm + wm + mi * 16 + (lane >> 2);
        #pragma unroll
        for (int ni = 0; ni < 4; ni++) {
            int c = bn + wn + ni * 8 + (lane & 3) * 2;
            if (r0 < M)
                *(float2*)(C + (size_t)r0 * Nf + c) = make_float2(acc[mi][ni][0], acc[mi][ni][1]);
            if (r0 + 8 < M)
                *(float2*)(C + (size_t)(r0 + 8) * Nf + c) = make_float2(acc[mi][ni][2], acc[mi][ni][3]);
        }
    }
}

// ======================= CSR aggregation (F=256) + bf16 split output =======================
__global__ void agg256(const float* __restrict__ H, const int* __restrict__ off,
                       const int* __restrict__ csrc, const float* __restrict__ dis,
                       const float* __restrict__ bias,
                       __nv_bfloat16* __restrict__ oh, __nv_bfloat16* __restrict__ ol) {
    int node = blockIdx.x * (blockDim.x >> 5) + (threadIdx.x >> 5);
    if (node >= N_NODES) return;
    int lane = threadIdx.x & 31;
    float dd = dis[node];
    float4 a0 = {0,0,0,0}, a1 = {0,0,0,0};
    int beg = off[node], end = off[node + 1];
    for (int e = beg; e < end; e++) {
        int s = csrc[e];
        float nrm = dis[s] * dd;
        const float4* hp = (const float4*)(H + (size_t)s * 256);
        float4 v0 = hp[lane * 2], v1 = hp[lane * 2 + 1];
        a0.x = fmaf(v0.x, nrm, a0.x); a0.y = fmaf(v0.y, nrm, a0.y);
        a0.z = fmaf(v0.z, nrm, a0.z); a0.w = fmaf(v0.w, nrm, a0.w);
        a1.x = fmaf(v1.x, nrm, a1.x); a1.y = fmaf(v1.y, nrm, a1.y);
        a1.z = fmaf(v1.z, nrm, a1.z); a1.w = fmaf(v1.w, nrm, a1.w);
    }
    float sl = dd * dd;
    const float4* gp = (const float4*)(H + (size_t)node * 256);
    float4 s0 = gp[lane * 2], s1 = gp[lane * 2 + 1];
    a0.x = fmaf(s0.x, sl, a0.x); a0.y = fmaf(s0.y, sl, a0.y);
    a0.z = fmaf(s0.z, sl, a0.z); a0.w = fmaf(s0.w, sl, a0.w);
    a1.x = fmaf(s1.x, sl, a1.x); a1.y = fmaf(s1.y, sl, a1.y);
    a1.z = fmaf(s1.z, sl, a1.z); a1.w = fmaf(s1.w, sl, a1.w);
    const float4* bp = (const float4*)bias;
    float4 b0 = bp[lane * 2], b1 = bp[lane * 2 + 1];
    float f[8];
    f[0] = fmaxf(a0.x + b0.x, 0.f); f[1] = fmaxf(a0.y + b0.y, 0.f);
    f[2] = fmaxf(a0.z + b0.z, 0.f); f[3] = fmaxf(a0.w + b0.w, 0.f);
    f[4] = fmaxf(a1.x + b1.x, 0.f); f[5] = fmaxf(a1.y + b1.y, 0.f);
    f[6] = fmaxf(a1.z + b1.z, 0.f); f[7] = fmaxf(a1.w + b1.w, 0.f);
    union { __nv_bfloat16 v[8]; uint4 u; } hv, lv;
    #pragma unroll
    for (int j = 0; j < 8; j++) split1(f[j], hv.v[j], lv.v[j]);
    *(uint4*)(oh + (size_t)node * 256 + lane * 8) = hv.u;
    *(uint4*)(ol + (size_t)node * 256 + lane * 8) = lv.u;
}

// ======================= last layer: F=128 agg fused into add-pool =======================
__global__ void agg_pool128(const float* __restrict__ H, const int* __restrict__ off,
                            const int* __restrict__ csrc, const float* __restrict__ dis,
                            const float* __restrict__ bias, float* __restrict__ pooled) {
    __shared__ float sm[N_CLS];
    int tid = threadIdx.x;
    if (tid < N_CLS) sm[tid] = 0.f;
    __syncthreads();
    int node = blockIdx.x * (blockDim.x >> 5) + (tid >> 5);
    int lane = tid & 31;
    if (node < N_NODES) {
        float dd = dis[node];
        float4 a = {0,0,0,0};
        int beg = off[node], end = off[node + 1];
        for (int e = beg; e < end; e++) {
            int s = csrc[e];
            float nrm = dis[s] * dd;
            float4 v = ((const float4*)(H + (size_t)s * 128))[lane];
            a.x = fmaf(v.x, nrm, a.x); a.y = fmaf(v.y, nrm, a.y);
            a.z = fmaf(v.z, nrm, a.z); a.w = fmaf(v.w, nrm, a.w);
        }
        float sl = dd * dd;
        float4 s4 = ((const float4*)(H + (size_t)node * 128))[lane];
        a.x = fmaf(s4.x, sl, a.x); a.y = fmaf(s4.y, sl, a.y);
        a.z = fmaf(s4.z, sl, a.z); a.w = fmaf(s4.w, sl, a.w);
        float4 b = ((const float4*)bias)[lane];
        a.x += b.x; a.y += b.y; a.z += b.z; a.w += b.w;
        atomicAdd(&sm[lane * 4 + 0], a.x);
        atomicAdd(&sm[lane * 4 + 1], a.y);
        atomicAdd(&sm[lane * 4 + 2], a.z);
        atomicAdd(&sm[lane * 4 + 3], a.w);
    }
    __syncthreads();
    if (tid < N_CLS) atomicAdd(&pooled[tid], sm[tid]);
}

// ======================= final =======================
__global__ void final_kernel(const float* __restrict__ pooled, float* __restrict__ out) {
    __shared__ float red[N_CLS];
    int f = threadIdx.x;
    float v = pooled[f];
    red[f] = v;
    __syncthreads();
    for (int s = N_CLS / 2; s > 0; s >>= 1) {
        if (f < s) red[f] = fmaxf(red[f], red[f + s]);
        __syncthreads();
    }
    float mx = red[0];
    __syncthreads();
    red[f] = expf(v - mx);
    __syncthreads();
    for (int s = N_CLS / 2; s > 0; s >>= 1) {
        if (f < s) red[f] += red[f + s];
        __syncthreads();
    }
    float lse = mx + logf(red[0]);
    out[f] = v;
    out[N_CLS + f] = v - lse;
}

// ======================= host =======================
extern "C" void kernel_launch(void* const* d_in, const int* in_sizes, int n_in,
                              void* d_out, int out_size) {
    const float* x  = (const float*)d_in[0];
    const int*   ei = (const int*)  d_in[1];
    const float* W1 = (const float*)d_in[2];
    const float* b1 = (const float*)d_in[3];
    const float* W2 = (const float*)d_in[4];
    const float* b2 = (const float*)d_in[5];
    const float* W3 = (const float*)d_in[6];
    const float* b3 = (const float*)d_in[7];
    const float* W4 = (const float*)d_in[8];
    const float* b4 = (const float*)d_in[9];
    float* out = (float*)d_out;

    const int* src = ei;
    const int* dst = ei + N_EDGES;

    float *C, *dis, *pooled;
    __nv_bfloat16 *ah, *al, *bh, *bl, *wth, *wtl;
    int *deg, *off, *cur, *csrc, *part;
    cudaGetSymbolAddress((void**)&C,      g_gemm);
    cudaGetSymbolAddress((void**)&ah,     g_ah);
    cudaGetSymbolAddress((void**)&al,     g_al);
    cudaGetSymbolAddress((void**)&bh,     g_bh);
    cudaGetSymbolAddress((void**)&bl,     g_bl);
    cudaGetSymbolAddress((void**)&wth,    g_wth);
    cudaGetSymbolAddress((void**)&wtl,    g_wtl);
    cudaGetSymbolAddress((void**)&dis,    g_dis);
    cudaGetSymbolAddress((void**)&pooled, g_pool);
    cudaGetSymbolAddress((void**)&deg,    g_deg);
    cudaGetSymbolAddress((void**)&off,    g_off);
    cudaGetSymbolAddress((void**)&cur,    g_cur);
    cudaGetSymbolAddress((void**)&csrc,   g_csrc);
    cudaGetSymbolAddress((void**)&part,   g_part);

    cudaFuncSetAttribute(bf16_gemm, cudaFuncAttributeMaxDynamicSharedMemorySize, GSMEM);

    // ---- CSR build + norms ----
    zero_i<<<(N_NODES + 255) / 256, 256>>>(deg, N_NODES);
    deg_count<<<(N_EDGES + 255) / 256, 256>>>(dst, deg);
    dis_kernel<<<(N_NODES + 255) / 256, 256>>>(deg, dis);
    part_reduce<<<NBLK, 256>>>(deg, part);
    scan_parts<<<1, 256>>>(part, off + N_NODES);
    block_scan<<<NBLK, 256>>>(deg, part, off, cur);
    place_edges<<<(N_EDGES + 255) / 256, 256>>>(src, dst, cur, csrc);

    const int AGG_BLOCKS = (N_NODES * 32 + 255) / 256;
    const int MT = (N_NODES + 127) / 128;     // 391 M-tiles
    dim3 g2(MT, 2), g1(MT, 1);

    // ---- split input ----
    split_x<<<(N_NODES * 256 + 255) / 256, 256>>>(x, ah, al, N_NODES * 256);

    // layer 1
    split_w<<<(256 * 256 + 255) / 256, 256>>>(W1, 256, 256, wth, wtl);
    bf16_gemm<<<g2, 256, GSMEM>>>(ah, al, wth, wtl, C, N_NODES, 256);
    agg256<<<AGG_BLOCKS, 256>>>(C, off, csrc, dis, b1, bh, bl);
    // layer 2
    split_w<<<(256 * 256 + 255) / 256, 256>>>(W2, 256, 256, wth, wtl);
    bf16_gemm<<<g2, 256, GSMEM>>>(bh, bl, wth, wtl, C, N_NODES, 256);
    agg256<<<AGG_BLOCKS, 256>>>(C, off, csrc, dis, b2, ah, al);
    // layer 3
    split_w<<<(256 * 256 + 255) / 256, 256>>>(W3, 256, 256, wth, wtl);
    bf16_gemm<<<g2, 256, GSMEM>>>(ah, al, wth, wtl, C, N_NODES, 256);
    agg256<<<AGG_BLOCKS, 256>>>(C, off, csrc, dis, b3, bh, bl);
    // layer 4 (N=128) + pool
    split_w<<<(256 * 128 + 255) / 256, 256>>>(W4, 256, 128, wth, wtl);
    bf16_gemm<<<g1, 256, GSMEM>>>(bh, bl, wth, wtl, C, N_NODES, 128);
    zero_f<<<1, N_CLS>>>(pooled, N_CLS);
    agg_pool128<<<AGG_BLOCKS, 256>>>(C, off, csrc, dis, b4, pooled);

    final_kernel<<<1, N_CLS>>>(pooled, out);
}

// round 17
// speedup vs baseline: 4.1412x; 1.3830x over previous
#include <cuda_runtime.h>
#include <cuda_bf16.h>
#include <cstdint>

#define N_NODES 50000
#define N_EDGES 300000
#define F_IN    256
#define HID     256
#define N_CLS   128

// ======================= helpers =======================
__device__ __forceinline__ uint32_t smem_u32(const void* p) {
    uint32_t a;
    asm("{ .reg .u64 t; cvta.to.shared.u64 t, %1; cvt.u32.u64 %0, t; }" : "=r"(a) : "l"(p));
    return a;
}
__device__ __forceinline__ void cp16(uint32_t dst, const void* src) {
    asm volatile("cp.async.cg.shared.global [%0], [%1], 16;" :: "r"(dst), "l"(src) : "memory");
}
__device__ __forceinline__ void ldmx4(uint32_t& r0, uint32_t& r1, uint32_t& r2, uint32_t& r3,
                                      uint32_t addr) {
    asm volatile("ldmatrix.sync.aligned.m8n8.x4.shared.b16 {%0,%1,%2,%3}, [%4];"
                 : "=r"(r0), "=r"(r1), "=r"(r2), "=r"(r3) : "r"(addr));
}
__device__ __forceinline__ void mma_bf16(float* d, const uint32_t* a, const uint32_t* b) {
    asm volatile("mma.sync.aligned.m16n8k16.row.col.f32.bf16.bf16.f32 "
                 "{%0,%1,%2,%3}, {%4,%5,%6,%7}, {%8,%9}, {%0,%1,%2,%3};"
                 : "+f"(d[0]), "+f"(d[1]), "+f"(d[2]), "+f"(d[3])
                 : "r"(a[0]), "r"(a[1]), "r"(a[2]), "r"(a[3]), "r"(b[0]), "r"(b[1]));
}
__device__ __forceinline__ void split1(float v, __nv_bfloat16& h, __nv_bfloat16& l) {
    h = __float2bfloat16(v);
    l = __float2bfloat16(v - __bfloat162float(h));
}

// ======================= scratch =======================
__device__ float         g_gemm[N_NODES * HID];          // fp32 GEMM output
__device__ __nv_bfloat16 g_ah[N_NODES * HID];
__device__ __nv_bfloat16 g_al[N_NODES * HID];
__device__ __nv_bfloat16 g_bh[N_NODES * HID];
__device__ __nv_bfloat16 g_bl[N_NODES * HID];
__device__ __nv_bfloat16 g_wth[HID * HID];
__device__ __nv_bfloat16 g_wtl[HID * HID];
__device__ float g_dis [N_NODES];
__device__ float g_pool[N_CLS];
__device__ int   g_deg [N_NODES];
__device__ int   g_off [N_NODES + 1];
__device__ int   g_cur [N_NODES];
__device__ int   g_csrc[N_EDGES];
__device__ int   g_part[256];

#define NBLK 196   // ceil(50000/256)

// ======================= small utils =======================
__global__ void zero_f(float* __restrict__ p, int n) {
    int i = blockIdx.x * blockDim.x + threadIdx.x;
    if (i < n) p[i] = 0.f;
}
__global__ void zero_i(int* __restrict__ p, int n) {
    int i = blockIdx.x * blockDim.x + threadIdx.x;
    if (i < n) p[i] = 0;
}
__global__ void deg_count(const int* __restrict__ dst, int* __restrict__ deg) {
    int i = blockIdx.x * blockDim.x + threadIdx.x;
    if (i < N_EDGES) atomicAdd(&deg[dst[i]], 1);
}
__global__ void dis_kernel(const int* __restrict__ deg, float* __restrict__ dis) {
    int i = blockIdx.x * blockDim.x + threadIdx.x;
    if (i < N_NODES) dis[i] = rsqrtf((float)deg[i] + 1.0f);
}

// --------- 3-phase scan ---------
__global__ void part_reduce(const int* __restrict__ deg, int* __restrict__ part) {
    int i = blockIdx.x * 256 + threadIdx.x;
    int v = (i < N_NODES) ? deg[i] : 0;
    #pragma unroll
    for (int o = 16; o; o >>= 1) v += __shfl_down_sync(0xFFFFFFFFu, v, o);
    __shared__ int ws[8];
    if ((threadIdx.x & 31) == 0) ws[threadIdx.x >> 5] = v;
    __syncthreads();
    if (threadIdx.x == 0) {
        int s = 0;
        #pragma unroll
        for (int j = 0; j < 8; j++) s += ws[j];
        part[blockIdx.x] = s;
    }
}
__global__ void scan_parts(int* __restrict__ part, int* __restrict__ total_out) {
    __shared__ int s[256];
    int t = threadIdx.x;
    int v = (t < NBLK) ? part[t] : 0;
    s[t] = v;
    __syncthreads();
    for (int d = 1; d < 256; d <<= 1) {
        int x = (t >= d) ? s[t - d] : 0;
        __syncthreads();
        s[t] += x;
        __syncthreads();
    }
    if (t < NBLK) part[t] = s[t] - v;
    if (t == 255) total_out[0] = s[255];
}
__global__ void block_scan(const int* __restrict__ deg, const int* __restrict__ part,
                           int* __restrict__ off, int* __restrict__ cur) {
    int i = blockIdx.x * 256 + threadIdx.x;
    int v = (i < N_NODES) ? deg[i] : 0;
    int lane = threadIdx.x & 31, w = threadIdx.x >> 5;
    int inc = v;
    #pragma unroll
    for (int o = 1; o < 32; o <<= 1) {
        int x = __shfl_up_sync(0xFFFFFFFFu, inc, o);
        if (lane >= o) inc += x;
    }
    __shared__ int ws[8], wo[8];
    if (lane == 31) ws[w] = inc;
    __syncthreads();
    if (threadIdx.x == 0) {
        int a = 0;
        #pragma unroll
        for (int j = 0; j < 8; j++) { wo[j] = a; a += ws[j]; }
    }
    __syncthreads();
    int excl = part[blockIdx.x] + wo[w] + inc - v;
    if (i < N_NODES) { off[i] = excl; cur[i] = excl; }
}
__global__ void place_edges(const int* __restrict__ src, const int* __restrict__ dst,
                            int* __restrict__ cur, int* __restrict__ csrc) {
    int e = blockIdx.x * blockDim.x + threadIdx.x;
    if (e < N_EDGES) {
        int pos = atomicAdd(&cur[dst[e]], 1);
        csrc[pos] = src[e];
    }
}

// --------- splits ---------
__global__ void split_x(const float* __restrict__ x, __nv_bfloat16* __restrict__ xh,
                        __nv_bfloat16* __restrict__ xl, int n) {
    int i = blockIdx.x * blockDim.x + threadIdx.x;
    if (i < n) {
        float v = x[i];
        __nv_bfloat16 h, l;
        split1(v, h, l);
        xh[i] = h;
        xl[i] = l;
    }
}
// W [K, N] row-major -> Wt hi/lo [N, K] bf16
__global__ void split_w(const float* __restrict__ W, int K, int N,
                        __nv_bfloat16* __restrict__ Wth, __nv_bfloat16* __restrict__ Wtl) {
    int i = blockIdx.x * blockDim.x + threadIdx.x;
    if (i < K * N) {
        int k = i / N, n = i - k * N;
        __nv_bfloat16 h, l;
        split1(W[i], h, l);
        Wth[(size_t)n * K + k] = h;
        Wtl[(size_t)n * K + k] = l;
    }
}

// ======================= bf16 split GEMM via mma.sync, 2-stage pipeline =======================
// C[M, Nf] = (Ah+Al)[M,256] @ (Wt hi+lo)[Nf,256]^T, CTA tile 128x128, K chunks of 64, 2 stages.
#define OFF_AH 0
#define OFF_AL 16384
#define OFF_BH 32768
#define OFF_BL 49152
#define STG    65536
#define GSMEM  131072

__device__ __forceinline__ void load_chunk64(
    const __nv_bfloat16* __restrict__ Ah, const __nv_bfloat16* __restrict__ Al,
    const __nv_bfloat16* __restrict__ Bh, const __nv_bfloat16* __restrict__ Bl,
    uint32_t st, int bm, int bn, int M, int kc, int lrow, int lcb, int lcol) {
    #pragma unroll
    for (int p = 0; p < 4; p++) {
        int r = p * 32 + lrow;
        uint32_t sw = (uint32_t)(r * 128 + (lcb ^ ((r & 7) << 4)));
        int gm = bm + r;
        if (gm > M - 1) gm = M - 1;
        cp16(st + OFF_AH + sw, Ah + (size_t)gm * 256 + kc + lcol);
        cp16(st + OFF_AL + sw, Al + (size_t)gm * 256 + kc + lcol);
        cp16(st + OFF_BH + sw, Bh + (size_t)(bn + r) * 256 + kc + lcol);
        cp16(st + OFF_BL + sw, Bl + (size_t)(bn + r) * 256 + kc + lcol);
    }
    asm volatile("cp.async.commit_group;" ::: "memory");
}

__global__ void __launch_bounds__(256, 1)
bf16_gemm(const __nv_bfloat16* __restrict__ Ah, const __nv_bfloat16* __restrict__ Al,
          const __nv_bfloat16* __restrict__ Bh, const __nv_bfloat16* __restrict__ Bl,
          float* __restrict__ C, int M, int Nf) {
    extern __shared__ char smem[];
    const uint32_t sbase = smem_u32(smem);
    const int tid = threadIdx.x;
    const int bm = blockIdx.x * 128, bn = blockIdx.y * 128;
    const int warp = tid >> 5, lane = tid & 31;
    const int wm = (warp & 1) * 64, wn = (warp >> 1) * 32;

    float acc[4][4][4];
    #pragma unroll
    for (int i = 0; i < 4; i++)
        #pragma unroll
        for (int j = 0; j < 4; j++)
            #pragma unroll
            for (int q = 0; q < 4; q++) acc[i][j][q] = 0.f;

    const int lrow = tid >> 3;          // 0..31
    const int lcb  = (tid & 7) * 16;    // byte col within 128B row
    const int lcol = (tid & 7) * 8;     // element col

    // prologue: queue chunks 0 and 1
    load_chunk64(Ah, Al, Bh, Bl, sbase,       bm, bn, M, 0,  lrow, lcb, lcol);
    load_chunk64(Ah, Al, Bh, Bl, sbase + STG, bm, bn, M, 64, lrow, lcb, lcol);

    #pragma unroll
    for (int c = 0; c < 4; c++) {
        if (c < 2)
            asm volatile("cp.async.wait_group 1;" ::: "memory");
        else
            asm volatile("cp.async.wait_group 0;" ::: "memory");
        __syncthreads();
        const uint32_t st = sbase + (c & 1) * STG;

        #pragma unroll
        for (int ks = 0; ks < 4; ks++) {
            const int kb = ks * 32 + ((lane >> 4) << 4);
            uint32_t bh[4][2], bl[4][2];
            #pragma unroll
            for (int g = 0; g < 2; g++) {
                int nr = wn + g * 16 + (lane & 15);
                uint32_t ad = st + OFF_BH + nr * 128 + (kb ^ ((nr & 7) << 4));
                uint32_t r0, r1, r2, r3;
                ldmx4(r0, r1, r2, r3, ad);
                bh[g * 2][0] = r0; bh[g * 2][1] = r2;
                bh[g * 2 + 1][0] = r1; bh[g * 2 + 1][1] = r3;
                ldmx4(r0, r1, r2, r3, ad + (OFF_BL - OFF_BH));
                bl[g * 2][0] = r0; bl[g * 2][1] = r2;
                bl[g * 2 + 1][0] = r1; bl[g * 2 + 1][1] = r3;
            }
            #pragma unroll
            for (int mi = 0; mi < 4; mi++) {
                int mr = wm + mi * 16 + (lane & 15);
                uint32_t ad = st + OFF_AH + mr * 128 + (kb ^ ((mr & 7) << 4));
                uint32_t ah[4], al[4];
                ldmx4(ah[0], ah[1], ah[2], ah[3], ad);
                ldmx4(al[0], al[1], al[2], al[3], ad + (OFF_AL - OFF_AH));
                #pragma unroll
                for (int ni = 0; ni < 4; ni++) {
                    mma_bf16(acc[mi][ni], ah, bh[ni]);   // hi*hi
                    mma_bf16(acc[mi][ni], ah, bl[ni]);   // hi*lo
                    mma_bf16(acc[mi][ni], al, bh[ni]);   // lo*hi
                }
            }
        }
        __syncthreads();       // all warps done reading this stage
        if (c < 2)
            load_chunk64(Ah, Al, Bh, Bl, sbase + (c & 1) * STG, bm, bn, M,
                         (c + 2) * 64, lrow, lcb, lcol);
    }

    // epilogue: fragment -> C
    #pragma unroll
    for (int mi = 0; mi < 4; mi++) {
        int r0 = bm + wm + mi * 16 + (lane >> 2);
        #pragma unroll
        for (int ni = 0; ni < 4; ni++) {
            int c = bn + wn + ni * 8 + (lane & 3) * 2;
            if (r0 < M)
                *(float2*)(C + (size_t)r0 * Nf + c) = make_float2(acc[mi][ni][0], acc[mi][ni][1]);
            if (r0 + 8 < M)
                *(float2*)(C + (size_t)(r0 + 8) * Nf + c) = make_float2(acc[mi][ni][2], acc[mi][ni][3]);
        }
    }
}

// ======================= CSR aggregation (F=256) + bf16 split output =======================
__global__ void agg256(const float* __restrict__ H, const int* __restrict__ off,
                       const int* __restrict__ csrc, const float* __restrict__ dis,
                       const float* __restrict__ bias,
                       __nv_bfloat16* __restrict__ oh, __nv_bfloat16* __restrict__ ol) {
    int node = blockIdx.x * (blockDim.x >> 5) + (threadIdx.x >> 5);
    if (node >= N_NODES) return;
    int lane = threadIdx.x & 31;
    float dd = dis[node];
    float4 a0 = {0,0,0,0}, a1 = {0,0,0,0};
    int beg = off[node], end = off[node + 1];
    for (int e = beg; e < end; e++) {
        int s = csrc[e];
        float nrm = dis[s] * dd;
        const float4* hp = (const float4*)(H + (size_t)s * 256);
        float4 v0 = hp[lane * 2], v1 = hp[lane * 2 + 1];
        a0.x = fmaf(v0.x, nrm, a0.x); a0.y = fmaf(v0.y, nrm, a0.y);
        a0.z = fmaf(v0.z, nrm, a0.z); a0.w = fmaf(v0.w, nrm, a0.w);
        a1.x = fmaf(v1.x, nrm, a1.x); a1.y = fmaf(v1.y, nrm, a1.y);
        a1.z = fmaf(v1.z, nrm, a1.z); a1.w = fmaf(v1.w, nrm, a1.w);
    }
    float sl = dd * dd;
    const float4* gp = (const float4*)(H + (size_t)node * 256);
    float4 s0 = gp[lane * 2], s1 = gp[lane * 2 + 1];
    a0.x = fmaf(s0.x, sl, a0.x); a0.y = fmaf(s0.y, sl, a0.y);
    a0.z = fmaf(s0.z, sl, a0.z); a0.w = fmaf(s0.w, sl, a0.w);
    a1.x = fmaf(s1.x, sl, a1.x); a1.y = fmaf(s1.y, sl, a1.y);
    a1.z = fmaf(s1.z, sl, a1.z); a1.w = fmaf(s1.w, sl, a1.w);
    const float4* bp = (const float4*)bias;
    float4 b0 = bp[lane * 2], b1 = bp[lane * 2 + 1];
    float f[8];
    f[0] = fmaxf(a0.x + b0.x, 0.f); f[1] = fmaxf(a0.y + b0.y, 0.f);
    f[2] = fmaxf(a0.z + b0.z, 0.f); f[3] = fmaxf(a0.w + b0.w, 0.f);
    f[4] = fmaxf(a1.x + b1.x, 0.f); f[5] = fmaxf(a1.y + b1.y, 0.f);
    f[6] = fmaxf(a1.z + b1.z, 0.f); f[7] = fmaxf(a1.w + b1.w, 0.f);
    union { __nv_bfloat16 v[8]; uint4 u; } hv, lv;
    #pragma unroll
    for (int j = 0; j < 8; j++) split1(f[j], hv.v[j], lv.v[j]);
    *(uint4*)(oh + (size_t)node * 256 + lane * 8) = hv.u;
    *(uint4*)(ol + (size_t)node * 256 + lane * 8) = lv.u;
}

// ======================= last layer: F=128 agg fused into add-pool =======================
__global__ void agg_pool128(const float* __restrict__ H, const int* __restrict__ off,
                            const int* __restrict__ csrc, const float* __restrict__ dis,
                            const float* __restrict__ bias, float* __restrict__ pooled) {
    __shared__ float sm[N_CLS];
    int tid = threadIdx.x;
    if (tid < N_CLS) sm[tid] = 0.f;
    __syncthreads();
    int node = blockIdx.x * (blockDim.x >> 5) + (tid >> 5);
    int lane = tid & 31;
    if (node < N_NODES) {
        float dd = dis[node];
        float4 a = {0,0,0,0};
        int beg = off[node], end = off[node + 1];
        for (int e = beg; e < end; e++) {
            int s = csrc[e];
            float nrm = dis[s] * dd;
            float4 v = ((const float4*)(H + (size_t)s * 128))[lane];
            a.x = fmaf(v.x, nrm, a.x); a.y = fmaf(v.y, nrm, a.y);
            a.z = fmaf(v.z, nrm, a.z); a.w = fmaf(v.w, nrm, a.w);
        }
        float sl = dd * dd;
        float4 s4 = ((const float4*)(H + (size_t)node * 128))[lane];
        a.x = fmaf(s4.x, sl, a.x); a.y = fmaf(s4.y, sl, a.y);
        a.z = fmaf(s4.z, sl, a.z); a.w = fmaf(s4.w, sl, a.w);
        float4 b = ((const float4*)bias)[lane];
        a.x += b.x; a.y += b.y; a.z += b.z; a.w += b.w;
        atomicAdd(&sm[lane * 4 + 0], a.x);
        atomicAdd(&sm[lane * 4 + 1], a.y);
        atomicAdd(&sm[lane * 4 + 2], a.z);
        atomicAdd(&sm[lane * 4 + 3], a.w);
    }
    __syncthreads();
    if (tid < N_CLS) atomicAdd(&pooled[tid], sm[tid]);
}

// ======================= final =======================
__global__ void final_kernel(const float* __restrict__ pooled, float* __restrict__ out) {
    __shared__ float red[N_CLS];
    int f = threadIdx.x;
    float v = pooled[f];
    red[f] = v;
    __syncthreads();
    for (int s = N_CLS / 2; s > 0; s >>= 1) {
        if (f < s) red[f] = fmaxf(red[f], red[f + s]);
        __syncthreads();
    }
    float mx = red[0];
    __syncthreads();
    red[f] = expf(v - mx);
    __syncthreads();
    for (int s = N_CLS / 2; s > 0; s >>= 1) {
        if (f < s) red[f] += red[f + s];
        __syncthreads();
    }
    float lse = mx + logf(red[0]);
    out[f] = v;
    out[N_CLS + f] = v - lse;
}

// ======================= host =======================
extern "C" void kernel_launch(void* const* d_in, const int* in_sizes, int n_in,
                              void* d_out, int out_size) {
    const float* x  = (const float*)d_in[0];
    const int*   ei = (const int*)  d_in[1];
    const float* W1 = (const float*)d_in[2];
    const float* b1 = (const float*)d_in[3];
    const float* W2 = (const float*)d_in[4];
    const float* b2 = (const float*)d_in[5];
    const float* W3 = (const float*)d_in[6];
    const float* b3 = (const float*)d_in[7];
    const float* W4 = (const float*)d_in[8];
    const float* b4 = (const float*)d_in[9];
    float* out = (float*)d_out;

    const int* src = ei;
    const int* dst = ei + N_EDGES;

    float *C, *dis, *pooled;
    __nv_bfloat16 *ah, *al, *bh, *bl, *wth, *wtl;
    int *deg, *off, *cur, *csrc, *part;
    cudaGetSymbolAddress((void**)&C,      g_gemm);
    cudaGetSymbolAddress((void**)&ah,     g_ah);
    cudaGetSymbolAddress((void**)&al,     g_al);
    cudaGetSymbolAddress((void**)&bh,     g_bh);
    cudaGetSymbolAddress((void**)&bl,     g_bl);
    cudaGetSymbolAddress((void**)&wth,    g_wth);
    cudaGetSymbolAddress((void**)&wtl,    g_wtl);
    cudaGetSymbolAddress((void**)&dis,    g_dis);
    cudaGetSymbolAddress((void**)&pooled, g_pool);
    cudaGetSymbolAddress((void**)&deg,    g_deg);
    cudaGetSymbolAddress((void**)&off,    g_off);
    cudaGetSymbolAddress((void**)&cur,    g_cur);
    cudaGetSymbolAddress((void**)&csrc,   g_csrc);
    cudaGetSymbolAddress((void**)&part,   g_part);

    cudaFuncSetAttribute(bf16_gemm, cudaFuncAttributeMaxDynamicSharedMemorySize, GSMEM);

    // ---- CSR build + norms ----
    zero_i<<<(N_NODES + 255) / 256, 256>>>(deg, N_NODES);
    deg_count<<<(N_EDGES + 255) / 256, 256>>>(dst, deg);
    dis_kernel<<<(N_NODES + 255) / 256, 256>>>(deg, dis);
    part_reduce<<<NBLK, 256>>>(deg, part);
    scan_parts<<<1, 256>>>(part, off + N_NODES);
    block_scan<<<NBLK, 256>>>(deg, part, off, cur);
    place_edges<<<(N_EDGES + 255) / 256, 256>>>(src, dst, cur, csrc);

    const int AGG_BLOCKS = (N_NODES * 32 + 255) / 256;
    const int MT = (N_NODES + 127) / 128;     // 391 M-tiles
    dim3 g2(MT, 2), g1(MT, 1);

    // ---- split input ----
    split_x<<<(N_NODES * 256 + 255) / 256, 256>>>(x, ah, al, N_NODES * 256);

    // layer 1
    split_w<<<(256 * 256 + 255) / 256, 256>>>(W1, 256, 256, wth, wtl);
    bf16_gemm<<<g2, 256, GSMEM>>>(ah, al, wth, wtl, C, N_NODES, 256);
    agg256<<<AGG_BLOCKS, 256>>>(C, off, csrc, dis, b1, bh, bl);
    // layer 2
    split_w<<<(256 * 256 + 255) / 256, 256>>>(W2, 256, 256, wth, wtl);
    bf16_gemm<<<g2, 256, GSMEM>>>(bh, bl, wth, wtl, C, N_NODES, 256);
    agg256<<<AGG_BLOCKS, 256>>>(C, off, csrc, dis, b2, ah, al);
    // layer 3
    split_w<<<(256 * 256 + 255) / 256, 256>>>(W3, 256, 256, wth, wtl);
    bf16_gemm<<<g2, 256, GSMEM>>>(ah, al, wth, wtl, C, N_NODES, 256);
    agg256<<<AGG_BLOCKS, 256>>>(C, off, csrc, dis, b3, bh, bl);
    // layer 4 (N=128) + pool
    split_w<<<(256 * 128 + 255) / 256, 256>>>(W4, 256, 128, wth, wtl);
    bf16_gemm<<<g1, 256, GSMEM>>>(bh, bl, wth, wtl, C, N_NODES, 128);
    zero_f<<<1, N_CLS>>>(pooled, N_CLS);
    agg_pool128<<<AGG_BLOCKS, 256>>>(C, off, csrc, dis, b4, pooled);

    final_kernel<<<1, N_CLS>>>(pooled, out);
}